// round 1
// baseline (speedup 1.0000x reference)
#include <cuda_runtime.h>

// Fused GridNet: encoder MLP -> bilinear grid gather -> FC head, one thread per point.
// FC1/FC2/FC3 use packed fma.rn.f32x2 (FFMA2) for 2x fp32 FMA throughput on sm_103a.

typedef unsigned long long u64;

__device__ __forceinline__ u64 pack2(float lo, float hi) {
    u64 r;
    asm("mov.b64 %0, {%1, %2};" : "=l"(r) : "f"(lo), "f"(hi));
    return r;
}
__device__ __forceinline__ float2 unpack2(u64 v) {
    float2 f;
    asm("mov.b64 {%0, %1}, %2;" : "=f"(f.x), "=f"(f.y) : "l"(v));
    return f;
}
__device__ __forceinline__ void fma2(u64 &d, u64 a, u64 b) {
    asm("fma.rn.f32x2 %0, %1, %2, %0;" : "+l"(d) : "l"(a), "l"(b));
}
__device__ __forceinline__ float leaky(float x) { return fmaxf(x, 0.01f * x); }
__device__ __forceinline__ float sigmoidf(float x) { return 1.0f / (1.0f + __expf(-x)); }

// Accumulate one input feature f (index gives weight row) into 64 packed FC1 accumulators.
__device__ __forceinline__ void accum_fc1(u64 *h1, const float *wrow, float f) {
    u64 fv = pack2(f, f);
    const ulonglong2 *w = (const ulonglong2 *)wrow;  // 16B-aligned shared row
#pragma unroll
    for (int q = 0; q < 16; q++) {
        ulonglong2 wq = w[q];
        fma2(h1[2 * q], fv, wq.x);
        fma2(h1[2 * q + 1], fv, wq.y);
    }
}

__global__ void __launch_bounds__(128) gridnet_fused(
    const float *__restrict__ pos, const float *__restrict__ dir,
    const float *__restrict__ pos_grid, const float *__restrict__ dir_grid,
    const float *__restrict__ enc_w1, const float *__restrict__ enc_b1,
    const float *__restrict__ enc_w2, const float *__restrict__ enc_b2,
    const float *__restrict__ fc_w1, const float *__restrict__ fc_b1,
    const float *__restrict__ fc_w2, const float *__restrict__ fc_b2,
    const float *__restrict__ fc_w3, const float *__restrict__ fc_b3,
    const float *__restrict__ fc_w4, const float *__restrict__ fc_b4,
    float *__restrict__ out, int n)
{
    __shared__ __align__(16) float sw1[64 * 64];
    __shared__ __align__(16) float sw2[64 * 16];
    __shared__ __align__(16) float sw3[16 * 8];
    __shared__ float sw4[24];
    __shared__ __align__(8) float sb1[64];
    __shared__ __align__(8) float sb2[16];
    __shared__ __align__(8) float sb3[8];
    __shared__ float sb4[3];
    __shared__ float senc[27];  // [0:8) enc_w1, [8:12) enc_b1, [12:24) enc_w2, [24:27) enc_b2

    const int tid = threadIdx.x;
    for (int i = tid; i < 64 * 64; i += 128) sw1[i] = fc_w1[i];
    for (int i = tid; i < 64 * 16; i += 128) sw2[i] = fc_w2[i];
    sw3[tid] = fc_w3[tid & 127];  // 128 elems, blockDim == 128
    if (tid < 64) sb1[tid] = fc_b1[tid];
    if (tid < 24) sw4[tid] = fc_w4[tid];
    if (tid < 16) sb2[tid] = fc_b2[tid];
    if (tid < 8) sb3[tid] = fc_b3[tid];
    if (tid < 3) sb4[tid] = fc_b4[tid];
    if (tid < 8) senc[tid] = enc_w1[tid];
    else if (tid < 12) senc[tid] = enc_b1[tid - 8];
    else if (tid < 24) senc[tid] = enc_w2[tid - 12];
    else if (tid < 27) senc[tid] = enc_b2[tid - 24];
    __syncthreads();

    const int idx = blockIdx.x * 128 + tid;
    if (idx >= n) return;

    // ---- encoders: 2->4 tanh -> 4->3 sigmoid (cols 0,1 used), scaled to grid coords
    float px, py, dx, dy;
    {
        float i0 = pos[2 * idx], i1 = pos[2 * idx + 1];
        float j0 = dir[2 * idx], j1 = dir[2 * idx + 1];
        float hp[4], hd[4];
#pragma unroll
        for (int j = 0; j < 4; j++) {
            hp[j] = tanhf(fmaf(i0, senc[j], fmaf(i1, senc[4 + j], senc[8 + j])));
            hd[j] = tanhf(fmaf(j0, senc[j], fmaf(j1, senc[4 + j], senc[8 + j])));
        }
        float zp0 = senc[24], zp1 = senc[25], zd0 = senc[24], zd1 = senc[25];
#pragma unroll
        for (int j = 0; j < 4; j++) {
            zp0 = fmaf(hp[j], senc[12 + j * 3 + 0], zp0);
            zp1 = fmaf(hp[j], senc[12 + j * 3 + 1], zp1);
            zd0 = fmaf(hd[j], senc[12 + j * 3 + 0], zd0);
            zd1 = fmaf(hd[j], senc[12 + j * 3 + 1], zd1);
        }
        px = sigmoidf(zp0) * 255.0f;
        py = sigmoidf(zp1) * 255.0f;
        dx = sigmoidf(zd0) * 255.0f;
        dy = sigmoidf(zd1) * 255.0f;
    }

    // ---- FC1 accumulators (64 outputs as 32 packed f32x2), init with bias
    u64 h1[32];
#pragma unroll
    for (int p = 0; p < 32; p++) h1[p] = pack2(sb1[2 * p], sb1[2 * p + 1]);

    // ---- bilinear gather from both grids, streaming features into FC1
#pragma unroll 1
    for (int g = 0; g < 2; g++) {
        const float *gbase = (g == 0) ? pos_grid : dir_grid;
        float x = (g == 0) ? px : dx;
        float y = (g == 0) ? py : dy;
        int x0 = min((int)x, 255), y0 = min((int)y, 255);
        float xf = x - (float)x0, yf = y - (float)y0;
        int x1 = min(x0 + 1, 255), y1 = min(y0 + 1, 255);
        const float4 *tl = (const float4 *)gbase + (y0 * 256 + x0) * 8;
        const float4 *tr = (const float4 *)gbase + (y0 * 256 + x1) * 8;
        const float4 *bl = (const float4 *)gbase + (y1 * 256 + x0) * 8;
        const float4 *br = (const float4 *)gbase + (y1 * 256 + x1) * 8;
        float wtl = (1.0f - xf) * (1.0f - yf);
        float wtr = xf * (1.0f - yf);
        float wbl = (1.0f - xf) * yf;
        float wbr = xf * yf;
#pragma unroll 2
        for (int c = 0; c < 8; c++) {
            float4 a = __ldg(tl + c), b = __ldg(tr + c);
            float4 d0 = __ldg(bl + c), e0 = __ldg(br + c);
            float f0 = wtl * a.x + wtr * b.x + wbl * d0.x + wbr * e0.x;
            float f1 = wtl * a.y + wtr * b.y + wbl * d0.y + wbr * e0.y;
            float f2 = wtl * a.z + wtr * b.z + wbl * d0.z + wbr * e0.z;
            float f3 = wtl * a.w + wtr * b.w + wbl * d0.w + wbr * e0.w;
            const float *wrow = sw1 + (g * 32 + c * 4) * 64;
            accum_fc1(h1, wrow + 0 * 64, f0);
            accum_fc1(h1, wrow + 1 * 64, f1);
            accum_fc1(h1, wrow + 2 * 64, f2);
            accum_fc1(h1, wrow + 3 * 64, f3);
        }
    }

    // ---- FC2: 64 -> 16 (packed)
    u64 h2[8];
#pragma unroll
    for (int p = 0; p < 8; p++) h2[p] = pack2(sb2[2 * p], sb2[2 * p + 1]);
#pragma unroll
    for (int p = 0; p < 32; p++) {
        float2 v = unpack2(h1[p]);
        float a0 = leaky(v.x), a1 = leaky(v.y);
        u64 a0v = pack2(a0, a0), a1v = pack2(a1, a1);
        const ulonglong2 *w0 = (const ulonglong2 *)(sw2 + (2 * p) * 16);
        const ulonglong2 *w1 = (const ulonglong2 *)(sw2 + (2 * p + 1) * 16);
#pragma unroll
        for (int q = 0; q < 4; q++) {
            ulonglong2 wa = w0[q];
            fma2(h2[2 * q], a0v, wa.x);
            fma2(h2[2 * q + 1], a0v, wa.y);
            ulonglong2 wb = w1[q];
            fma2(h2[2 * q], a1v, wb.x);
            fma2(h2[2 * q + 1], a1v, wb.y);
        }
    }

    // ---- FC3: 16 -> 8 (packed)
    u64 h3[4];
#pragma unroll
    for (int p = 0; p < 4; p++) h3[p] = pack2(sb3[2 * p], sb3[2 * p + 1]);
#pragma unroll
    for (int p = 0; p < 8; p++) {
        float2 v = unpack2(h2[p]);
        float a0 = leaky(v.x), a1 = leaky(v.y);
        u64 a0v = pack2(a0, a0), a1v = pack2(a1, a1);
        const ulonglong2 *w0 = (const ulonglong2 *)(sw3 + (2 * p) * 8);
        const ulonglong2 *w1 = (const ulonglong2 *)(sw3 + (2 * p + 1) * 8);
#pragma unroll
        for (int q = 0; q < 2; q++) {
            ulonglong2 wa = w0[q];
            fma2(h3[2 * q], a0v, wa.x);
            fma2(h3[2 * q + 1], a0v, wa.y);
            ulonglong2 wb = w1[q];
            fma2(h3[2 * q], a1v, wb.x);
            fma2(h3[2 * q + 1], a1v, wb.y);
        }
    }

    // ---- FC4: 8 -> 3, leaky, sigmoid * 255
    float o0 = sb4[0], o1 = sb4[1], o2 = sb4[2];
#pragma unroll
    for (int p = 0; p < 4; p++) {
        float2 v = unpack2(h3[p]);
        float a0 = leaky(v.x), a1 = leaky(v.y);
        int i0 = 2 * p, i1 = 2 * p + 1;
        o0 = fmaf(a0, sw4[i0 * 3 + 0], o0);
        o1 = fmaf(a0, sw4[i0 * 3 + 1], o1);
        o2 = fmaf(a0, sw4[i0 * 3 + 2], o2);
        o0 = fmaf(a1, sw4[i1 * 3 + 0], o0);
        o1 = fmaf(a1, sw4[i1 * 3 + 1], o1);
        o2 = fmaf(a1, sw4[i1 * 3 + 2], o2);
    }
    o0 = sigmoidf(leaky(o0)) * 255.0f;
    o1 = sigmoidf(leaky(o1)) * 255.0f;
    o2 = sigmoidf(leaky(o2)) * 255.0f;

    out[idx * 3 + 0] = o0;
    out[idx * 3 + 1] = o1;
    out[idx * 3 + 2] = o2;
}

extern "C" void kernel_launch(void *const *d_in, const int *in_sizes, int n_in,
                              void *d_out, int out_size)
{
    const float *pos = (const float *)d_in[0];
    const float *dir = (const float *)d_in[1];
    const float *pos_grid = (const float *)d_in[2];
    const float *dir_grid = (const float *)d_in[3];
    const float *enc_w1 = (const float *)d_in[4];
    const float *enc_b1 = (const float *)d_in[5];
    const float *enc_w2 = (const float *)d_in[6];
    const float *enc_b2 = (const float *)d_in[7];
    const float *fc_w1 = (const float *)d_in[8];
    const float *fc_b1 = (const float *)d_in[9];
    const float *fc_w2 = (const float *)d_in[10];
    const float *fc_b2 = (const float *)d_in[11];
    const float *fc_w3 = (const float *)d_in[12];
    const float *fc_b3 = (const float *)d_in[13];
    const float *fc_w4 = (const float *)d_in[14];
    const float *fc_b4 = (const float *)d_in[15];
    float *out = (float *)d_out;

    int n = in_sizes[0] / 2;  // pos is [N, 2]
    int blocks = (n + 127) / 128;
    gridnet_fused<<<blocks, 128>>>(pos, dir, pos_grid, dir_grid,
                                   enc_w1, enc_b1, enc_w2, enc_b2,
                                   fc_w1, fc_b1, fc_w2, fc_b2,
                                   fc_w3, fc_b3, fc_w4, fc_b4,
                                   out, n);
}

// round 3
// speedup vs baseline: 1.7787x; 1.7787x over previous
#include <cuda_runtime.h>
#include <stdint.h>

typedef unsigned long long u64;
typedef unsigned int u32;

// ---------------- constant-memory weights (uniform LDCU path) ----------------
__constant__ __align__(16) float cW1[64 * 64];  // [i][j], j contiguous
__constant__ __align__(16) float cW2[64 * 16];
__constant__ __align__(16) float cW3[16 * 8];
__constant__ __align__(16) float cW4[8 * 3];
__constant__ __align__(16) float cB1[64];
__constant__ __align__(16) float cB2[16];
__constant__ __align__(16) float cB3[8];
__constant__ __align__(16) float cB4[3];
__constant__ __align__(16) float cEnc[27];  // [0:8) w1, [8:12) b1, [12:24) w2, [24:27) b2

// ---------------- helpers ----------------
static __device__ __forceinline__ u64 pack2(float lo, float hi) {
    u64 r; asm("mov.b64 %0, {%1, %2};" : "=l"(r) : "f"(lo), "f"(hi)); return r;
}
static __device__ __forceinline__ float2 unpack2(u64 v) {
    float2 f; asm("mov.b64 {%0, %1}, %2;" : "=f"(f.x), "=f"(f.y) : "l"(v)); return f;
}
static __device__ __forceinline__ void fma2(u64 &d, u64 a, u64 b) {
    asm("fma.rn.f32x2 %0, %1, %2, %0;" : "+l"(d) : "l"(a), "l"(b));
}
static __device__ __forceinline__ float leaky(float x) { return fmaxf(x, 0.01f * x); }
static __device__ __forceinline__ float sigmoidf(float x) { return 1.0f / (1.0f + __expf(-x)); }
// tanh(x) = 2*sigmoid(2x) - 1 (fast path, MUFU-based)
static __device__ __forceinline__ float tanh_fast(float x) {
    return fmaf(2.0f, sigmoidf(2.0f * x), -1.0f);
}

// Accumulate feature fa (point A) / fb (point B) against one FC1 weight row.
// Weight loads are warp-uniform -> LDCU, shared by both points.
static __device__ __forceinline__ void accum2(u64 *hA, u64 *hB, const float *wrow,
                                              float fa, float fb) {
    u64 fav = pack2(fa, fa), fbv = pack2(fb, fb);
    const ulonglong2 *w = (const ulonglong2 *)wrow;
#pragma unroll
    for (int q = 0; q < 16; q++) {
        ulonglong2 wq = w[q];
        fma2(hA[2 * q], fav, wq.x);
        fma2(hA[2 * q + 1], fav, wq.y);
        fma2(hB[2 * q], fbv, wq.x);
        fma2(hB[2 * q + 1], fbv, wq.y);
    }
}

// encoder: 2->4 tanh -> 4->3 sigmoid (cols 0,1) -> scale by 255
static __device__ __forceinline__ void encode(float i0, float i1, float &x, float &y) {
    float h[4];
#pragma unroll
    for (int j = 0; j < 4; j++)
        h[j] = tanh_fast(fmaf(i0, cEnc[j], fmaf(i1, cEnc[4 + j], cEnc[8 + j])));
    float z0 = cEnc[24], z1 = cEnc[25];
#pragma unroll
    for (int j = 0; j < 4; j++) {
        z0 = fmaf(h[j], cEnc[12 + j * 3 + 0], z0);
        z1 = fmaf(h[j], cEnc[12 + j * 3 + 1], z1);
    }
    x = sigmoidf(z0) * 255.0f;
    y = sigmoidf(z1) * 255.0f;
}

struct Corners {
    const float4 *tl, *tr, *bl, *br;
    float wtl, wtr, wbl, wbr;
};
static __device__ __forceinline__ Corners corners(const float *gbase, float x, float y) {
    Corners c;
    int x0 = min((int)x, 255), y0 = min((int)y, 255);
    float xf = x - (float)x0, yf = y - (float)y0;
    int x1 = min(x0 + 1, 255), y1 = min(y0 + 1, 255);
    c.tl = (const float4 *)gbase + (y0 * 256 + x0) * 8;
    c.tr = (const float4 *)gbase + (y0 * 256 + x1) * 8;
    c.bl = (const float4 *)gbase + (y1 * 256 + x0) * 8;
    c.br = (const float4 *)gbase + (y1 * 256 + x1) * 8;
    c.wtl = (1.0f - xf) * (1.0f - yf);
    c.wtr = xf * (1.0f - yf);
    c.wbl = (1.0f - xf) * yf;
    c.wbr = xf * yf;
    return c;
}
static __device__ __forceinline__ float4 blend(const Corners &c, int off) {
    float4 a = __ldg(c.tl + off), b = __ldg(c.tr + off);
    float4 d = __ldg(c.bl + off), e = __ldg(c.br + off);
    float4 f;
    f.x = c.wtl * a.x + c.wtr * b.x + c.wbl * d.x + c.wbr * e.x;
    f.y = c.wtl * a.y + c.wtr * b.y + c.wbl * d.y + c.wbr * e.y;
    f.z = c.wtl * a.z + c.wtr * b.z + c.wbl * d.z + c.wbr * e.z;
    f.w = c.wtl * a.w + c.wtr * b.w + c.wbl * d.w + c.wbr * e.w;
    return f;
}

// FC3 (16->8) + FC4 (8->3) + sigmoid*255 for one point
static __device__ __forceinline__ float3 head(const float *a2) {
    u64 h3[4];
#pragma unroll
    for (int q = 0; q < 4; q++) h3[q] = pack2(cB3[2 * q], cB3[2 * q + 1]);
#pragma unroll
    for (int j = 0; j < 16; j++) {
        float a = a2[j];
        u64 av = pack2(a, a);
        const ulonglong2 *w = (const ulonglong2 *)(cW3 + j * 8);
#pragma unroll
        for (int q = 0; q < 2; q++) {
            ulonglong2 wq = w[q];
            fma2(h3[2 * q], av, wq.x);
            fma2(h3[2 * q + 1], av, wq.y);
        }
    }
    float o0 = cB4[0], o1 = cB4[1], o2 = cB4[2];
#pragma unroll
    for (int q = 0; q < 4; q++) {
        float2 v = unpack2(h3[q]);
        float a0 = leaky(v.x), a1 = leaky(v.y);
        int i0 = 2 * q, i1 = 2 * q + 1;
        o0 = fmaf(a0, cW4[i0 * 3 + 0], o0);
        o1 = fmaf(a0, cW4[i0 * 3 + 1], o1);
        o2 = fmaf(a0, cW4[i0 * 3 + 2], o2);
        o0 = fmaf(a1, cW4[i1 * 3 + 0], o0);
        o1 = fmaf(a1, cW4[i1 * 3 + 1], o1);
        o2 = fmaf(a1, cW4[i1 * 3 + 2], o2);
    }
    float3 r;
    r.x = sigmoidf(leaky(o0)) * 255.0f;
    r.y = sigmoidf(leaky(o1)) * 255.0f;
    r.z = sigmoidf(leaky(o2)) * 255.0f;
    return r;
}

// ---------------- kernel: 2 points per thread ----------------
__global__ void __launch_bounds__(128) gridnet_cmem(
    const float *__restrict__ pos, const float *__restrict__ dir,
    const float *__restrict__ pos_grid, const float *__restrict__ dir_grid,
    float *__restrict__ out, int n)
{
    const int tid = threadIdx.x;
    const int base = blockIdx.x * 256;
    const int pA = base + tid;
    const int pB = base + 128 + tid;
    const int cA = min(pA, n - 1);
    const int cB = min(pB, n - 1);

    // encoders -> grid coords for both points, both grids
    float pxA, pyA, dxA, dyA, pxB, pyB, dxB, dyB;
    {
        float a0 = pos[2 * cA], a1 = pos[2 * cA + 1];
        float b0 = pos[2 * cB], b1 = pos[2 * cB + 1];
        float e0 = dir[2 * cA], e1 = dir[2 * cA + 1];
        float f0 = dir[2 * cB], f1 = dir[2 * cB + 1];
        encode(a0, a1, pxA, pyA);
        encode(b0, b1, pxB, pyB);
        encode(e0, e1, dxA, dyA);
        encode(f0, f1, dxB, dyB);
    }

    // FC1 accumulators for both points (64 outs each as 32 packed f32x2)
    u64 h1A[32], h1B[32];
#pragma unroll
    for (int q = 0; q < 32; q++) {
        u64 b = pack2(cB1[2 * q], cB1[2 * q + 1]);
        h1A[q] = b;
        h1B[q] = b;
    }

    // gather + blend + stream into FC1 (weights via uniform constant loads)
#pragma unroll 1
    for (int g = 0; g < 2; g++) {
        const float *gbase = (g == 0) ? pos_grid : dir_grid;
        Corners crA = corners(gbase, (g == 0) ? pxA : dxA, (g == 0) ? pyA : dyA);
        Corners crB = corners(gbase, (g == 0) ? pxB : dxB, (g == 0) ? pyB : dyB);
#pragma unroll 2
        for (int c = 0; c < 8; c++) {
            float4 fA = blend(crA, c);
            float4 fB = blend(crB, c);
            const float *wrow = cW1 + (g * 32 + c * 4) * 64;
            accum2(h1A, h1B, wrow + 0 * 64, fA.x, fB.x);
            accum2(h1A, h1B, wrow + 1 * 64, fA.y, fB.y);
            accum2(h1A, h1B, wrow + 2 * 64, fA.z, fB.z);
            accum2(h1A, h1B, wrow + 3 * 64, fA.w, fB.w);
        }
    }

    // FC2: 64 -> 16, both points, uniform weight loads
    u64 h2A[8], h2B[8];
#pragma unroll
    for (int q = 0; q < 8; q++) {
        u64 b = pack2(cB2[2 * q], cB2[2 * q + 1]);
        h2A[q] = b;
        h2B[q] = b;
    }
#pragma unroll
    for (int p = 0; p < 32; p++) {
        float2 vA = unpack2(h1A[p]);
        float2 vB = unpack2(h1B[p]);
        float aA0 = leaky(vA.x), aA1 = leaky(vA.y);
        float aB0 = leaky(vB.x), aB1 = leaky(vB.y);
        u64 aA0v = pack2(aA0, aA0), aA1v = pack2(aA1, aA1);
        u64 aB0v = pack2(aB0, aB0), aB1v = pack2(aB1, aB1);
        const ulonglong2 *w0 = (const ulonglong2 *)(cW2 + (2 * p) * 16);
        const ulonglong2 *w1 = (const ulonglong2 *)(cW2 + (2 * p + 1) * 16);
#pragma unroll
        for (int q = 0; q < 4; q++) {
            ulonglong2 wa = w0[q];
            fma2(h2A[2 * q], aA0v, wa.x);
            fma2(h2A[2 * q + 1], aA0v, wa.y);
            fma2(h2B[2 * q], aB0v, wa.x);
            fma2(h2B[2 * q + 1], aB0v, wa.y);
            ulonglong2 wb = w1[q];
            fma2(h2A[2 * q], aA1v, wb.x);
            fma2(h2A[2 * q + 1], aA1v, wb.y);
            fma2(h2B[2 * q], aB1v, wb.x);
            fma2(h2B[2 * q + 1], aB1v, wb.y);
        }
    }

    // leaky(H2+0) -> FC3/FC4 head per point
    float a2A[16], a2B[16];
#pragma unroll
    for (int q = 0; q < 8; q++) {
        float2 vA = unpack2(h2A[q]);
        float2 vB = unpack2(h2B[q]);
        a2A[2 * q] = leaky(vA.x);
        a2A[2 * q + 1] = leaky(vA.y);
        a2B[2 * q] = leaky(vB.x);
        a2B[2 * q + 1] = leaky(vB.y);
    }
    float3 oA = head(a2A);
    float3 oB = head(a2B);

    if (pA < n) {
        out[pA * 3 + 0] = oA.x;
        out[pA * 3 + 1] = oA.y;
        out[pA * 3 + 2] = oA.z;
    }
    if (pB < n) {
        out[pB * 3 + 0] = oB.x;
        out[pB * 3 + 1] = oB.y;
        out[pB * 3 + 2] = oB.z;
    }
}

extern "C" void kernel_launch(void *const *d_in, const int *in_sizes, int n_in,
                              void *d_out, int out_size)
{
    const float *pos = (const float *)d_in[0];
    const float *dir = (const float *)d_in[1];
    const float *pos_grid = (const float *)d_in[2];
    const float *dir_grid = (const float *)d_in[3];

    // Stage weights into constant memory (D2D async copies: graph-capturable)
    cudaMemcpyToSymbolAsync(cEnc, d_in[4], 8 * sizeof(float), 0, cudaMemcpyDeviceToDevice, 0);
    cudaMemcpyToSymbolAsync(cEnc, d_in[5], 4 * sizeof(float), 8 * sizeof(float), cudaMemcpyDeviceToDevice, 0);
    cudaMemcpyToSymbolAsync(cEnc, d_in[6], 12 * sizeof(float), 12 * sizeof(float), cudaMemcpyDeviceToDevice, 0);
    cudaMemcpyToSymbolAsync(cEnc, d_in[7], 3 * sizeof(float), 24 * sizeof(float), cudaMemcpyDeviceToDevice, 0);
    cudaMemcpyToSymbolAsync(cW1, d_in[8], 64 * 64 * sizeof(float), 0, cudaMemcpyDeviceToDevice, 0);
    cudaMemcpyToSymbolAsync(cB1, d_in[9], 64 * sizeof(float), 0, cudaMemcpyDeviceToDevice, 0);
    cudaMemcpyToSymbolAsync(cW2, d_in[10], 64 * 16 * sizeof(float), 0, cudaMemcpyDeviceToDevice, 0);
    cudaMemcpyToSymbolAsync(cB2, d_in[11], 16 * sizeof(float), 0, cudaMemcpyDeviceToDevice, 0);
    cudaMemcpyToSymbolAsync(cW3, d_in[12], 16 * 8 * sizeof(float), 0, cudaMemcpyDeviceToDevice, 0);
    cudaMemcpyToSymbolAsync(cB3, d_in[13], 8 * sizeof(float), 0, cudaMemcpyDeviceToDevice, 0);
    cudaMemcpyToSymbolAsync(cW4, d_in[14], 8 * 3 * sizeof(float), 0, cudaMemcpyDeviceToDevice, 0);
    cudaMemcpyToSymbolAsync(cB4, d_in[15], 3 * sizeof(float), 0, cudaMemcpyDeviceToDevice, 0);

    float *out = (float *)d_out;
    int n = in_sizes[0] / 2;
    int blocks = (n + 255) / 256;
    gridnet_cmem<<<blocks, 128>>>(pos, dir, pos_grid, dir_grid, out, n);
}